// round 5
// baseline (speedup 1.0000x reference)
#include <cuda_runtime.h>
#include <cooperative_groups.h>
#include <cstdint>
#include <math.h>

namespace cg = cooperative_groups;

#define BLOCK 512
#define CLUSTER 4
#define CAP 32
#define FCAP 512

// shared-memory layout (in floats). Per CTA: 2 heads, 64 e-columns.
#define OFF_X0    0        // 512   X buffer A: [e 0..255][h 0..1]
#define OFF_X1    512      // 512   X buffer B
#define OFF_SCAL  1024     // 192   per-stage column scales [3][64]
#define OFF_CNT   1216     // 64    per-column correction count (int)
#define OFF_FCNT  1280     // 64    flat-list count (int, padded)
#define OFF_COLP7 1344     // 2048  correction d-index [64][CAP] (int)
#define OFF_COLC  3392     // 6144  correction values [3][64][CAP]
#define OFF_FPACK 9536     // 512   packed (d7*64+el)<<12 | k  (int)
#define OFF_FC6   10048    // 512   c6 per flat entry (int)
#define OFF_RED   10560    // 2048  partials [16 dch][2 h][64 e]
#define OFF_P1T   12608    // 16384 p1 tile [256 d][64 e]; becomes M cache
#define OFF_P3T   28992    // 16384 p3 tile [256 d][64 e]
#define SMEM_FLOATS 45376
#define SMEM_BYTES (SMEM_FLOATS * 4)   // 181,504 B

extern __shared__ float smem[];

__device__ __forceinline__ void cp_async16(uint32_t saddr, const void* gptr) {
    asm volatile("cp.async.cg.shared.global [%0], [%1], 16;\n"
                 :: "r"(saddr), "l"(gptr));
}

__global__ void __cluster_dims__(CLUSTER, 1, 1) __launch_bounds__(BLOCK, 1)
chain_kernel(const float* __restrict__ p1, const float* __restrict__ p2,
             const float* __restrict__ p3, const float* __restrict__ p4,
             const int* __restrict__ p5, const int* __restrict__ p6,
             const int* __restrict__ p7, const int* __restrict__ p8,
             const float* __restrict__ p9, const float* __restrict__ p10,
             const float* __restrict__ p11, const float* __restrict__ p12,
             const float* __restrict__ p13, const float* __restrict__ p14,
             const float* __restrict__ p15, const float* __restrict__ p16,
             float* __restrict__ out, int K)
{
    cg::cluster_group cluster = cg::this_cluster();
    const int tid  = (int)threadIdx.x;
    const int rank = (int)cluster.block_rank();        // e-segment 0..3
    const int cid  = (int)blockIdx.x >> 2;             // 0..35
    const int b    = cid / 6;                          // batch 0..5
    const int h0   = (cid % 6) * 2;                    // first head of pair
    const int e0   = rank * 64;                        // column base

    float* X0     = smem + OFF_X0;
    float* X1     = smem + OFF_X1;
    float* scal   = smem + OFF_SCAL;
    float* colc   = smem + OFF_COLC;
    float* red    = smem + OFF_RED;
    float* p1t    = smem + OFF_P1T;
    float* p3t    = smem + OFF_P3T;
    int*   colcnt = (int*)(smem + OFF_CNT);
    int*   fcnt   = (int*)(smem + OFF_FCNT);
    int*   colp7  = (int*)(smem + OFF_COLP7);
    int*   fpack  = (int*)(smem + OFF_FPACK);
    int*   fc6    = (int*)(smem + OFF_FC6);

    // ---------------- 0: async copies of p1/p3 e-seg tiles (fire & forget) --------
    {
        const float* g1 = p1 + b * 65536 + e0;
        const float* g3 = p3 + b * 65536 + e0;
        uint32_t s1 = (uint32_t)__cvta_generic_to_shared(p1t);
        uint32_t s3 = (uint32_t)__cvta_generic_to_shared(p3t);
        #pragma unroll
        for (int it = 0; it < 8; it++) {
            int c   = tid + it * BLOCK;
            int row = c >> 4;
            int q   = (c & 15) << 2;
            cp_async16(s1 + (row * 64 + q) * 4, g1 + row * 256 + q);
            cp_async16(s3 + (row * 64 + q) * 4, g3 + row * 256 + q);
        }
        asm volatile("cp.async.commit_group;\n" ::: "memory");
    }

    // ---------------- 1: prep (overlapped with copies) ----------------
    if (tid < 64) { colcnt[tid] = 0; if (tid == 0) fcnt[0] = 0; }

    // X0[d*2+h] = p2[(h0+h)*1536 + b*256 + d]
    for (int i = tid; i < 512; i += BLOCK) {
        int h = i >> 8, d = i & 255;
        X0[d * 2 + h] = p2[(h0 + h) * 1536 + b * 256 + d];
    }

    if (tid < 64) {
        float fr[3] = { p9[0],  p12[0], p15[0] };
        float ph[3] = { p10[0], p13[0], p16[0] };
        float t = (float)(e0 + tid);
        #pragma unroll
        for (int s = 0; s < 3; s++) {
            float a  = t * 6.2831853071795864f;
            a = a * fr[s] + ph[s];
            float sv = sinf(a);
            float m  = sv * sv * 0.1f + 0.95f;
            scal[s * 64 + tid] = (s == 1) ? m : (1.0f / m);
        }
    }
    __syncthreads();

    // collect matching scatter entries into flat list
    for (int k = tid; k < K; k += BLOCK) {
        if (p5[k] == b) {
            int e8 = p8[k];
            if ((e8 >> 6) == rank) {
                int j = atomicAdd(fcnt, 1);
                if (j < FCAP) {
                    fpack[j] = ((p7[k] * 64 + (e8 & 63)) << 12) | k;
                    fc6[j]   = p6[k];
                }
            }
        }
    }
    asm volatile("cp.async.wait_group 0;\n" ::: "memory");
    __syncthreads();   // flat list + tiles visible

    // last-index-wins per (d7,el); winners -> per-column correction lists
    {
        int n = fcnt[0]; if (n > FCAP) n = FCAP;
        for (int i = tid; i < n; i += BLOCK) {
            int me  = fpack[i];
            int key = me >> 12;
            bool win = true;
            for (int j = 0; j < n; j++) {
                int oth = fpack[j];
                if ((oth >> 12) == key && oth > me) { win = false; break; }
            }
            if (win) {
                int d7 = key >> 6, el = key & 63, c6 = fc6[i];
                float pb = p1t[d7 * 64 + el];
                int j = atomicAdd(&colcnt[el], 1);
                if (j < CAP) {
                    colp7[el * CAP + j] = d7;
                    colc[0 * 2048 + el * CAP + j] = p4 [b * 256 + c6] - pb;
                    colc[1 * 2048 + el * CAP + j] = p11[b * 256 + c6] - pb;
                    colc[2 * 2048 + el * CAP + j] = p14[b * 256 + c6] - pb;
                }
            }
        }
    }
    __syncthreads();

    // ---------------- 3-stage chain ----------------
    const int dch = tid >> 5;      // 0..15 : d-chunk (16 d each)
    const int ep  = tid & 31;      // 0..31 : e-column pair
    const int el2 = ep * 2;

    float* McB = p1t + dch * 16 * 64 + el2;
    float* P3B = p3t + dch * 16 * 64 + el2;

    for (int s = 0; s < 3; s++) {
        const float* Xin  = (s & 1) ? X1 : X0;
        float*       Xout = (s & 1) ? X0 : X1;

        float a00 = 0.f, a01 = 0.f, a10 = 0.f, a11 = 0.f;  // [h][e]
        const float2* Xd = (const float2*)(Xin + dch * 16 * 2);

        if (s == 0) {
            #pragma unroll
            for (int i = 0; i < 16; i++) {
                float2 a = *(const float2*)(McB + i * 64);
                float2 c = *(const float2*)(P3B + i * 64);
                float mx = fmaf(c.x, 0.975f, a.x);
                float my = fmaf(c.y, 0.975f, a.y);
                *(float2*)(McB + i * 64) = make_float2(mx, my);
                float2 x = Xd[i];                       // (h0,h1) broadcast
                a00 += x.x * mx;  a01 += x.x * my;
                a10 += x.y * mx;  a11 += x.y * my;
            }
        } else {
            #pragma unroll
            for (int i = 0; i < 16; i++) {
                float2 m = *(const float2*)(McB + i * 64);
                float2 x = Xd[i];
                a00 += x.x * m.x;  a01 += x.x * m.y;
                a10 += x.y * m.x;  a11 += x.y * m.y;
            }
        }

        // sparse corrections (warp 0 handles its 2 columns)
        if (dch == 0) {
            #pragma unroll
            for (int cc = 0; cc < 2; cc++) {
                int elc = el2 + cc;
                int n = colcnt[elc]; if (n > CAP) n = CAP;
                for (int j = 0; j < n; j++) {
                    int   d7 = colp7[elc * CAP + j];
                    float cv = colc[s * 2048 + elc * CAP + j];
                    float2 x = *(const float2*)(Xin + d7 * 2);
                    if (cc == 0) { a00 += x.x * cv;  a10 += x.y * cv; }
                    else         { a01 += x.x * cv;  a11 += x.y * cv; }
                }
            }
        }

        // partials: red[dch][h][e]
        *(float2*)&red[(dch * 2 + 0) * 64 + el2] = make_float2(a00, a01);
        *(float2*)&red[(dch * 2 + 1) * 64 + el2] = make_float2(a10, a11);
        __syncthreads();

        // reduce 16 partials, scale, emit (128 outputs)
        if (tid < 128) {
            int h = tid >> 6, elc = tid & 63;
            float sum = 0.0f;
            #pragma unroll
            for (int dc = 0; dc < 16; dc++) sum += red[(dc * 2 + h) * 64 + elc];
            sum *= scal[s * 64 + elc];
            if (s < 2) Xout[(e0 + elc) * 2 + h] = sum;
            else       out[(h0 + h) * 1536 + b * 256 + e0 + elc] = sum;
        }

        if (s < 2) {
            cluster.sync();   // own X segment visible cluster-wide
            // pull 3 peer segments (32 float4 each)
            if (tid < 96) {
                int pidx = tid >> 5;
                int off  = tid & 31;
                unsigned sr = (unsigned)((rank + 1 + pidx) & 3);
                float* dst = Xout + sr * 128 + off * 4;
                const float* peer = cluster.map_shared_rank(dst, sr);
                *(float4*)dst = *(const float4*)peer;
            }
            __syncthreads();
        }
    }

    cluster.sync();   // no CTA exits while peers may still read its SMEM
}

extern "C" void kernel_launch(void* const* d_in, const int* in_sizes, int n_in,
                              void* d_out, int out_size)
{
    (void)n_in; (void)out_size;
    cudaFuncSetAttribute(chain_kernel,
                         cudaFuncAttributeMaxDynamicSharedMemorySize, SMEM_BYTES);
    chain_kernel<<<36 * CLUSTER, BLOCK, SMEM_BYTES>>>(
        (const float*)d_in[0],  (const float*)d_in[1],
        (const float*)d_in[2],  (const float*)d_in[3],
        (const int*)  d_in[4],  (const int*)  d_in[5],
        (const int*)  d_in[6],  (const int*)  d_in[7],
        (const float*)d_in[8],  (const float*)d_in[9],
        (const float*)d_in[10], (const float*)d_in[11],
        (const float*)d_in[12], (const float*)d_in[13],
        (const float*)d_in[14], (const float*)d_in[15],
        (float*)d_out, in_sizes[4]);
}

// round 6
// speedup vs baseline: 1.3376x; 1.3376x over previous
#include <cuda_runtime.h>
#include <cooperative_groups.h>
#include <cstdint>
#include <math.h>

namespace cg = cooperative_groups;

#define BLOCK 1024
#define CLUSTER 4
#define CAP 32
#define FCAP 512

// shared-memory layout (floats)
#define OFF_X0    0        // 3072  X buffer A: [e 0..255][h 0..11]
#define OFF_X1    3072     // 3072  X buffer B
#define OFF_SCAL  6144     // 192   per-stage column scales [3][64]
#define OFF_CNT   6336     // 64    per-column correction count (int)
#define OFF_FCNT  6400     // 64    flat count (int, padded)
#define OFF_COLP7 6464     // 2048  correction d-index [64][CAP] (int)
#define OFF_COLC  8512     // 6144  correction values [3][64][CAP]
#define OFF_FPACK 14656    // 512   packed (d7*64+el)<<12 | k (int)
#define OFF_FC6   15168    // 512   c6 per flat entry (int)
#define OFF_RED   15680    // 12288 partials [16][12][64]; FIRST reused as scan arrays
#define OFF_MC    27968    // 16384 M cache [256 d][64 e]
#define SMEM_FLOATS 44352
#define SMEM_BYTES (SMEM_FLOATS * 4)   // 177,408 B

// scan arrays alias the red region (dead before partials are written)
#define S5_OFF (OFF_RED + 0)
#define S7_OFF (OFF_RED + 2048)
#define S8_OFF (OFF_RED + 4096)
#define S6_OFF (OFF_RED + 6144)

extern __shared__ float smem[];

__device__ __forceinline__ void cp_async16(uint32_t saddr, const void* gptr) {
    asm volatile("cp.async.cg.shared.global [%0], [%1], 16;\n"
                 :: "r"(saddr), "l"(gptr));
}

__global__ void __cluster_dims__(CLUSTER, 1, 1) __launch_bounds__(BLOCK, 1)
chain_kernel(const float* __restrict__ p1, const float* __restrict__ p2,
             const float* __restrict__ p3, const float* __restrict__ p4,
             const int* __restrict__ p5, const int* __restrict__ p6,
             const int* __restrict__ p7, const int* __restrict__ p8,
             const float* __restrict__ p9, const float* __restrict__ p10,
             const float* __restrict__ p11, const float* __restrict__ p12,
             const float* __restrict__ p13, const float* __restrict__ p14,
             const float* __restrict__ p15, const float* __restrict__ p16,
             float* __restrict__ out, int K)
{
    cg::cluster_group cluster = cg::this_cluster();
    const int tid  = (int)threadIdx.x;
    const int rank = (int)cluster.block_rank();   // e-segment 0..3
    const int b    = (int)blockIdx.x >> 2;        // batch 0..5
    const int e0   = rank * 64;

    float* X0     = smem + OFF_X0;
    float* X1     = smem + OFF_X1;
    float* scal   = smem + OFF_SCAL;
    float* colc   = smem + OFF_COLC;
    float* red    = smem + OFF_RED;
    float* Mc     = smem + OFF_MC;
    int*   colcnt = (int*)(smem + OFF_CNT);
    int*   fcnt   = (int*)(smem + OFF_FCNT);
    int*   colp7  = (int*)(smem + OFF_COLP7);
    int*   fpack  = (int*)(smem + OFF_FPACK);
    int*   fc6    = (int*)(smem + OFF_FC6);
    const int* s5 = (const int*)(smem + S5_OFF);
    const int* s7 = (const int*)(smem + S7_OFF);
    const int* s8 = (const int*)(smem + S8_OFF);
    const int* s6 = (const int*)(smem + S6_OFF);

    const int KC = (K < 2048) ? K : 2048;

    // ---- A: async copies of scatter-index arrays into (future) red region ----
    {
        uint32_t sb = (uint32_t)__cvta_generic_to_shared(smem + OFF_RED);
        const int* src[4] = { p5, p7, p8, p6 };
        int nchunk = (KC + 3) >> 2;               // 16B chunks per array
        #pragma unroll
        for (int it = 0; it < 2; it++) {
            int idx = tid + it * BLOCK;
            int a = idx >> 9, c = idx & 511;
            if (c < nchunk)
                cp_async16(sb + (a * 2048 + c * 4) * 4, src[a] + c * 4);
        }
        asm volatile("cp.async.commit_group;\n" ::: "memory");
    }

    // ---- B: zero counters, transpose-load X0, compute mod scales ----
    if (tid < 64) { colcnt[tid] = 0; if (tid == 0) fcnt[0] = 0; }

    for (int i = tid; i < 3072; i += BLOCK) {     // 3 iters
        int h = i >> 8, d = i & 255;
        X0[d * 12 + h] = p2[h * 1536 + b * 256 + d];
    }

    if (tid < 64) {
        float fr[3] = { p9[0],  p12[0], p15[0] };
        float ph[3] = { p10[0], p13[0], p16[0] };
        float t = (float)(e0 + tid);
        #pragma unroll
        for (int s = 0; s < 3; s++) {
            float a  = t * 6.2831853071795864f;
            a = a * fr[s] + ph[s];
            float sv = sinf(a);
            float m  = sv * sv * 0.1f + 0.95f;
            scal[s * 64 + tid] = (s == 1) ? m : (1.0f / m);
        }
    }
    __syncthreads();    // X0 + counters visible

    // ---- thread mapping for compute ----
    const int hg  = tid >> 9;          // 0/1 : head group (6 heads)
    const int r   = tid & 511;
    const int dch = r >> 5;            // 0..15 : d-chunk (16 d)
    const int ep  = r & 31;            // 0..31 : e-column pair
    const int el2 = ep * 2;

    const float* P1 = p1 + b * 65536 + dch * 16 * 256 + e0 + el2;
    const float* P3 = p3 + b * 65536 + dch * 16 * 256 + e0 + el2;
    float* McB = Mc + dch * 16 * 64 + el2;

    float acc[12];
    #pragma unroll
    for (int i = 0; i < 12; i++) acc[i] = 0.0f;

    // ---- C: stage-0 dense accumulation from GLOBAL (hides cp.async + prep) ----
    {
        const float* Xr = X0 + dch * 16 * 12 + hg * 6;
        #pragma unroll 4
        for (int i = 0; i < 16; i++) {
            float2 a = *(const float2*)(P1 + i * 256);
            float2 c = *(const float2*)(P3 + i * 256);
            float mx = fmaf(c.x, 0.975f, a.x);
            float my = fmaf(c.y, 0.975f, a.y);
            if (hg == 0) *(float2*)(McB + i * 64) = make_float2(mx, my);
            float2 xa = *(const float2*)(Xr + i * 12);
            float2 xb = *(const float2*)(Xr + i * 12 + 2);
            float2 xc = *(const float2*)(Xr + i * 12 + 4);
            acc[0]  += xa.x * mx;  acc[1]  += xa.x * my;
            acc[2]  += xa.y * mx;  acc[3]  += xa.y * my;
            acc[4]  += xb.x * mx;  acc[5]  += xb.x * my;
            acc[6]  += xb.y * mx;  acc[7]  += xb.y * my;
            acc[8]  += xc.x * mx;  acc[9]  += xc.x * my;
            acc[10] += xc.y * mx;  acc[11] += xc.y * my;
        }
    }

    asm volatile("cp.async.wait_group 0;\n" ::: "memory");
    __syncthreads();    // scan arrays visible everywhere

    // ---- D: scan (pure smem) -> flat list ----
    #pragma unroll
    for (int it = 0; it < 2; it++) {
        int k = tid + it * BLOCK;
        if (k < KC && s5[k] == b) {
            int e8 = s8[k];
            if ((e8 >> 6) == rank) {
                int j = atomicAdd(fcnt, 1);
                if (j < FCAP) {
                    fpack[j] = ((s7[k] * 64 + (e8 & 63)) << 12) | k;
                    fc6[j]   = s6[k];
                }
            }
        }
    }
    __syncthreads();

    // ---- E: last-index-wins dedup -> correction lists (global gathers, 1 latency) ----
    {
        int n = fcnt[0]; if (n > FCAP) n = FCAP;
        for (int i = tid; i < n; i += BLOCK) {
            int me  = fpack[i];
            int key = me >> 12;
            bool win = true;
            for (int j = 0; j < n; j++) {
                int oth = fpack[j];
                if ((oth >> 12) == key && oth > me) { win = false; break; }
            }
            if (win) {
                int d7 = key >> 6, el = key & 63, c6 = fc6[i];
                float pb = p1[b * 65536 + d7 * 256 + e0 + el];
                int j = atomicAdd(&colcnt[el], 1);
                if (j < CAP) {
                    colp7[el * CAP + j] = d7;
                    colc[0 * 2048 + el * CAP + j] = p4 [b * 256 + c6] - pb;
                    colc[1 * 2048 + el * CAP + j] = p11[b * 256 + c6] - pb;
                    colc[2 * 2048 + el * CAP + j] = p14[b * 256 + c6] - pb;
                }
            }
        }
    }
    __syncthreads();    // correction lists ready; red region free for partials

    // ---- stages 0..2: corrections + reduce + exchange (stage0 acc already done) ----
    for (int s = 0; s < 3; s++) {
        const float* Xin  = (s & 1) ? X1 : X0;
        float*       Xout = (s & 1) ? X0 : X1;

        if (s > 0) {
            #pragma unroll
            for (int i = 0; i < 12; i++) acc[i] = 0.0f;
            const float* Xr = Xin + dch * 16 * 12 + hg * 6;
            #pragma unroll 4
            for (int i = 0; i < 16; i++) {
                float2 m  = *(const float2*)(McB + i * 64);
                float2 xa = *(const float2*)(Xr + i * 12);
                float2 xb = *(const float2*)(Xr + i * 12 + 2);
                float2 xc = *(const float2*)(Xr + i * 12 + 4);
                acc[0]  += xa.x * m.x;  acc[1]  += xa.x * m.y;
                acc[2]  += xa.y * m.x;  acc[3]  += xa.y * m.y;
                acc[4]  += xb.x * m.x;  acc[5]  += xb.x * m.y;
                acc[6]  += xb.y * m.x;  acc[7]  += xb.y * m.y;
                acc[8]  += xc.x * m.x;  acc[9]  += xc.x * m.y;
                acc[10] += xc.y * m.x;  acc[11] += xc.y * m.y;
            }
        }

        // sparse corrections: the 2 warps with dch==0 (one per head group)
        if (dch == 0) {
            #pragma unroll
            for (int cc = 0; cc < 2; cc++) {
                int elc = el2 + cc;
                int n = colcnt[elc]; if (n > CAP) n = CAP;
                for (int j = 0; j < n; j++) {
                    int   d7 = colp7[elc * CAP + j];
                    float cv = colc[s * 2048 + elc * CAP + j];
                    const float* xr = Xin + d7 * 12 + hg * 6;
                    float2 xa = *(const float2*)(xr);
                    float2 xb = *(const float2*)(xr + 2);
                    float2 xc = *(const float2*)(xr + 4);
                    acc[0  + cc] += xa.x * cv;  acc[2  + cc] += xa.y * cv;
                    acc[4  + cc] += xb.x * cv;  acc[6  + cc] += xb.y * cv;
                    acc[8  + cc] += xc.x * cv;  acc[10 + cc] += xc.y * cv;
                }
            }
        }

        // partials: red[dch][h][e]
        #pragma unroll
        for (int j = 0; j < 6; j++) {
            int h = hg * 6 + j;
            *(float2*)&red[(dch * 12 + h) * 64 + el2] =
                make_float2(acc[2 * j], acc[2 * j + 1]);
        }
        __syncthreads();

        // reduce 16 partials, scale, emit
        if (tid < 768) {
            int h = tid >> 6, elc = tid & 63;
            float sum = 0.0f;
            #pragma unroll
            for (int dc = 0; dc < 16; dc++) sum += red[(dc * 12 + h) * 64 + elc];
            sum *= scal[s * 64 + elc];
            if (s < 2) Xout[(e0 + elc) * 12 + h] = sum;
            else       out[h * 1536 + b * 256 + e0 + elc] = sum;
        }

        if (s < 2) {
            cluster.sync();   // own X segment visible cluster-wide
            if (tid < 576) {  // pull 3 peer segments (192 float4 each)
                int pidx = tid / 192;
                int off  = tid % 192;
                unsigned sr = (unsigned)((rank + 1 + pidx) & 3);
                float* dst = Xout + sr * 768 + off * 4;
                const float* peer = cluster.map_shared_rank(dst, sr);
                *(float4*)dst = *(const float4*)peer;
            }
            __syncthreads();
        } else {
            __syncthreads();  // red reuse safety across loop exit (none) — keep minimal
        }
    }

    cluster.sync();   // no CTA exits while peers may still read its SMEM
}

extern "C" void kernel_launch(void* const* d_in, const int* in_sizes, int n_in,
                              void* d_out, int out_size)
{
    (void)n_in; (void)out_size;
    cudaFuncSetAttribute(chain_kernel,
                         cudaFuncAttributeMaxDynamicSharedMemorySize, SMEM_BYTES);
    chain_kernel<<<6 * CLUSTER, BLOCK, SMEM_BYTES>>>(
        (const float*)d_in[0],  (const float*)d_in[1],
        (const float*)d_in[2],  (const float*)d_in[3],
        (const int*)  d_in[4],  (const int*)  d_in[5],
        (const int*)  d_in[6],  (const int*)  d_in[7],
        (const float*)d_in[8],  (const float*)d_in[9],
        (const float*)d_in[10], (const float*)d_in[11],
        (const float*)d_in[12], (const float*)d_in[13],
        (const float*)d_in[14], (const float*)d_in[15],
        (float*)d_out, in_sizes[4]);
}